// round 1
// baseline (speedup 1.0000x reference)
#include <cuda_runtime.h>
#include <math.h>

// Problem constants
#define BATCH 32
#define CIN   128
#define HH    56
#define WW    56
#define OUTC  128
#define KSZ   3
#define HIDDEN 32
#define TEMPERATURE 31.0f
#define HWPIX (HH*WW)          // 3136

// Conv tiling
#define OT  32                 // output channels per block
#define TH  4                  // output rows per block
#define CCH 8                  // input channels per SMEM chunk
#define TPB (WW*TH)            // 224 threads

// Per-sample mixing coefficients computed by the attention kernel.
__device__ float g_attn[BATCH][2];

// ---------------------------------------------------------------------------
// Kernel 1: global-avg-pool -> fc1(relu) -> fc2 -> softmax(./T)
// One block per batch sample, 256 threads (8 warps).
// ---------------------------------------------------------------------------
__global__ void attn_kernel(const float* __restrict__ x,
                            const float* __restrict__ fc1_w,   // [HIDDEN, CIN]
                            const float* __restrict__ fc2_w)   // [2, HIDDEN]
{
    const int b    = blockIdx.x;
    const int tid  = threadIdx.x;
    const int warp = tid >> 5;
    const int lane = tid & 31;

    __shared__ float pooled[CIN];
    __shared__ float hid[HIDDEN];
    __shared__ float logits[2];

    // Pooling: warp w handles channels w, w+8, ... (coalesced 32-lane reads)
    for (int c = warp; c < CIN; c += 8) {
        const float* xp = x + ((size_t)b * CIN + c) * HWPIX;
        float s = 0.f;
        for (int i = lane; i < HWPIX; i += 32) s += xp[i];
        #pragma unroll
        for (int off = 16; off; off >>= 1) s += __shfl_xor_sync(0xffffffffu, s, off);
        if (lane == 0) pooled[c] = s * (1.0f / (float)HWPIX);
    }
    __syncthreads();

    // fc1 + relu
    if (tid < HIDDEN) {
        const float* fw = fc1_w + tid * CIN;
        float h = 0.f;
        #pragma unroll 4
        for (int c = 0; c < CIN; ++c) h += pooled[c] * fw[c];
        hid[tid] = fmaxf(h, 0.f);
    }
    __syncthreads();

    // fc2
    if (tid < 2) {
        const float* fw = fc2_w + tid * HIDDEN;
        float l = 0.f;
        #pragma unroll
        for (int j = 0; j < HIDDEN; ++j) l += hid[j] * fw[j];
        logits[tid] = l;
    }
    __syncthreads();

    // softmax over K=2 with temperature
    if (tid == 0) {
        float l0 = logits[0] * (1.0f / TEMPERATURE);
        float l1 = logits[1] * (1.0f / TEMPERATURE);
        float m  = fmaxf(l0, l1);
        float e0 = __expf(l0 - m);
        float e1 = __expf(l1 - m);
        float inv = 1.0f / (e0 + e1);
        g_attn[b][0] = e0 * inv;
        g_attn[b][1] = e1 * inv;
    }
}

// ---------------------------------------------------------------------------
// Kernel 2: per-sample 3x3 conv (stride 1, pad 1) with attention-aggregated
// weights: w_b = a0*W0 + a1*W1 (aggregated once per chunk into SMEM).
// Grid: (H/TH, OUTC/OT, BATCH). Block: (WW, TH) = 224 threads.
// Thread register tile: TH rows x 8 output channels.
// ---------------------------------------------------------------------------
__global__ void __launch_bounds__(TPB)
dyn_conv_kernel(const float* __restrict__ x,
                const float* __restrict__ cw,   // [OUTC, CIN, 3, 3]
                const float* __restrict__ cb,   // [OUTC]
                const float* __restrict__ dw,   // [OUTC, CIN, 3, 3]
                const float* __restrict__ db,   // [OUTC]
                float* __restrict__ out)
{
    __shared__ float sx[CCH][TH + 2][WW + 2];     // input halo tile
    __shared__ float swt[OT][CCH * 9];            // aggregated weights

    const int b     = blockIdx.z;
    const int obase = blockIdx.y * OT;
    const int hbase = blockIdx.x * TH;
    const int tx    = threadIdx.x;                // 0..55 (output col)
    const int ty    = threadIdx.y;                // 0..3  (o-group)
    const int tid   = ty * WW + tx;

    const float a0 = g_attn[b][0];
    const float a1 = g_attn[b][1];

    float acc[TH][8];
    #pragma unroll
    for (int r = 0; r < TH; ++r)
        #pragma unroll
        for (int oo = 0; oo < 8; ++oo) acc[r][oo] = 0.f;

    const float* xb = x + (size_t)b * CIN * HWPIX;

    for (int ccb = 0; ccb < CIN; ccb += CCH) {
        __syncthreads();

        // Stage input tile: channels [ccb, ccb+CCH), rows hbase-1..hbase+TH,
        // cols -1..WW (zero-padded halo).
        for (int i = tid; i < CCH * (TH + 2) * (WW + 2); i += TPB) {
            int c   = i / ((TH + 2) * (WW + 2));
            int rem = i % ((TH + 2) * (WW + 2));
            int rr  = rem / (WW + 2);
            int col = rem % (WW + 2);
            int hin = hbase + rr - 1;
            int win = col - 1;
            float v = 0.f;
            if (hin >= 0 && hin < HH && win >= 0 && win < WW)
                v = xb[(size_t)(ccb + c) * HWPIX + hin * WW + win];
            sx[c][rr][col] = v;
        }

        // Stage aggregated weights for this (o-tile, c-chunk).
        for (int i = tid; i < OT * CCH * 9; i += TPB) {
            int o   = i / (CCH * 9);
            int rem = i % (CCH * 9);
            int c   = rem / 9;
            int k   = rem % 9;
            size_t gi = ((size_t)(obase + o) * CIN + (ccb + c)) * 9 + k;
            swt[o][rem] = a0 * cw[gi] + a1 * dw[gi];
        }
        __syncthreads();

        // Compute: per input channel, load a 6x3 input window into regs
        // (reused across 8 output channels), weights reused across 4 rows.
        #pragma unroll 2
        for (int c = 0; c < CCH; ++c) {
            float xv[TH + 2][3];
            #pragma unroll
            for (int rr = 0; rr < TH + 2; ++rr)
                #pragma unroll
                for (int jj = 0; jj < 3; ++jj)
                    xv[rr][jj] = sx[c][rr][tx + jj];

            #pragma unroll
            for (int oo = 0; oo < 8; ++oo) {
                const float* wp = &swt[ty * 8 + oo][c * 9];
                #pragma unroll
                for (int i3 = 0; i3 < 3; ++i3)
                    #pragma unroll
                    for (int j3 = 0; j3 < 3; ++j3) {
                        float wt = wp[i3 * 3 + j3];
                        #pragma unroll
                        for (int r = 0; r < TH; ++r)
                            acc[r][oo] = fmaf(wt, xv[r + i3][j3], acc[r][oo]);
                    }
            }
        }
    }

    // Epilogue: add aggregated bias and store.
    #pragma unroll
    for (int oo = 0; oo < 8; ++oo) {
        int o = obase + ty * 8 + oo;
        float bias = a0 * cb[o] + a1 * db[o];
        #pragma unroll
        for (int r = 0; r < TH; ++r) {
            out[(((size_t)b * OUTC + o) * HH + (hbase + r)) * WW + tx] =
                acc[r][oo] + bias;
        }
    }
}

// ---------------------------------------------------------------------------
// Harness entry point.
// Input order (metadata): x, common_weight, common_bias, dyn_weight,
//                         dyn_bias, fc1_w, fc2_w. Output: float32 [32,128,56,56].
// ---------------------------------------------------------------------------
extern "C" void kernel_launch(void* const* d_in, const int* in_sizes, int n_in,
                              void* d_out, int out_size)
{
    const float* x     = (const float*)d_in[0];
    const float* cw    = (const float*)d_in[1];
    const float* cb    = (const float*)d_in[2];
    const float* dw    = (const float*)d_in[3];
    const float* db    = (const float*)d_in[4];
    const float* fc1_w = (const float*)d_in[5];
    const float* fc2_w = (const float*)d_in[6];
    float* out = (float*)d_out;

    attn_kernel<<<BATCH, 256>>>(x, fc1_w, fc2_w);

    dim3 grid(HH / TH, OUTC / OT, BATCH);   // (14, 4, 32)
    dim3 block(WW, TH);                     // (56, 4) = 224 threads
    dyn_conv_kernel<<<grid, block>>>(x, cw, cb, dw, db, out);
}

// round 2
// speedup vs baseline: 1.2250x; 1.2250x over previous
#include <cuda_runtime.h>
#include <math.h>

// Problem constants
#define BATCH 32
#define CIN   128
#define HH    56
#define WW    56
#define OUTC  128
#define HIDDEN 32
#define TEMPERATURE 31.0f
#define HWPIX (HH*WW)          // 3136

// Conv tiling
#define OT  32                 // output channels per block
#define TH  4                  // output rows per block
#define CCH 8                  // input channels per SMEM chunk
#define TPB (WW*TH)            // 224 threads

__device__ float g_attn[BATCH][2];

// ---------------------------------------------------------------------------
// Packed fp32x2 helpers (sm_103a). ptxas never emits FFMA2 from C++.
// ---------------------------------------------------------------------------
__device__ __forceinline__ unsigned long long bcast2(float v) {
    unsigned long long r;
    asm("mov.b64 %0, {%1, %1};" : "=l"(r) : "r"(__float_as_uint(v)));
    return r;
}
__device__ __forceinline__ void fma2(unsigned long long& d,
                                     unsigned long long a,
                                     unsigned long long b) {
    asm("fma.rn.f32x2 %0, %1, %2, %0;" : "+l"(d) : "l"(a), "l"(b));
}
__device__ __forceinline__ void unpack2(unsigned long long v, float& lo, float& hi) {
    asm("mov.b64 {%0, %1}, %2;" : "=f"(lo), "=f"(hi) : "l"(v));
}

// ---------------------------------------------------------------------------
// Kernel 1: global-avg-pool -> fc1(relu) -> fc2 -> softmax(./T)
// ---------------------------------------------------------------------------
__global__ void attn_kernel(const float* __restrict__ x,
                            const float* __restrict__ fc1_w,   // [HIDDEN, CIN]
                            const float* __restrict__ fc2_w)   // [2, HIDDEN]
{
    const int b    = blockIdx.x;
    const int tid  = threadIdx.x;
    const int warp = tid >> 5;
    const int lane = tid & 31;

    __shared__ float pooled[CIN];
    __shared__ float hid[HIDDEN];
    __shared__ float logits[2];

    for (int c = warp; c < CIN; c += 8) {
        const float* xp = x + ((size_t)b * CIN + c) * HWPIX;
        float s = 0.f;
        for (int i = lane; i < HWPIX; i += 32) s += xp[i];
        #pragma unroll
        for (int off = 16; off; off >>= 1) s += __shfl_xor_sync(0xffffffffu, s, off);
        if (lane == 0) pooled[c] = s * (1.0f / (float)HWPIX);
    }
    __syncthreads();

    if (tid < HIDDEN) {
        const float* fw = fc1_w + tid * CIN;
        float h = 0.f;
        #pragma unroll 4
        for (int c = 0; c < CIN; ++c) h += pooled[c] * fw[c];
        hid[tid] = fmaxf(h, 0.f);
    }
    __syncthreads();

    if (tid < 2) {
        const float* fw = fc2_w + tid * HIDDEN;
        float l = 0.f;
        #pragma unroll
        for (int j = 0; j < HIDDEN; ++j) l += hid[j] * fw[j];
        logits[tid] = l;
    }
    __syncthreads();

    if (tid == 0) {
        float l0 = logits[0] * (1.0f / TEMPERATURE);
        float l1 = logits[1] * (1.0f / TEMPERATURE);
        float m  = fmaxf(l0, l1);
        float e0 = __expf(l0 - m);
        float e1 = __expf(l1 - m);
        float inv = 1.0f / (e0 + e1);
        g_attn[b][0] = e0 * inv;
        g_attn[b][1] = e1 * inv;
    }
}

// ---------------------------------------------------------------------------
// Kernel 2: per-sample 3x3 conv with aggregated weights, fp32x2 packed math.
// Output-channel pairs (2p, 2p+1) share one packed accumulator; weights are
// staged interleaved so one LDS.64 yields the packed weight pair.
// Grid: (H/TH, OUTC/OT, BATCH). Block: (WW, TH) = 224 threads.
// ---------------------------------------------------------------------------
__global__ void __launch_bounds__(TPB)
dyn_conv_kernel(const float* __restrict__ x,
                const float* __restrict__ cw,   // [OUTC, CIN, 3, 3]
                const float* __restrict__ cb,   // [OUTC]
                const float* __restrict__ dw,   // [OUTC, CIN, 3, 3]
                const float* __restrict__ db,   // [OUTC]
                float* __restrict__ out)
{
    __shared__ float  sx[CCH][TH + 2][WW + 2];          // input halo tile
    __shared__ float2 swt2[OT / 2][CCH * 9];            // packed (o even, o odd)

    const int b     = blockIdx.z;
    const int obase = blockIdx.y * OT;
    const int hbase = blockIdx.x * TH;
    const int tx    = threadIdx.x;                // 0..55  (output col)
    const int ty    = threadIdx.y;                // 0..3   (o-group)
    const int tid   = ty * WW + tx;

    const float a0 = g_attn[b][0];
    const float a1 = g_attn[b][1];

    // acc2[r][p] packs outputs (o = ty*8 + 2p, +1) at row r.
    unsigned long long acc2[TH][4];
    #pragma unroll
    for (int r = 0; r < TH; ++r)
        #pragma unroll
        for (int p = 0; p < 4; ++p) acc2[r][p] = 0ull;

    const float* xb = x + (size_t)b * CIN * HWPIX;

    for (int ccb = 0; ccb < CIN; ccb += CCH) {
        __syncthreads();

        // Stage input tile (zero-padded halo).
        for (int i = tid; i < CCH * (TH + 2) * (WW + 2); i += TPB) {
            int c   = i / ((TH + 2) * (WW + 2));
            int rem = i % ((TH + 2) * (WW + 2));
            int rr  = rem / (WW + 2);
            int col = rem % (WW + 2);
            int hin = hbase + rr - 1;
            int win = col - 1;
            float v = 0.f;
            if (hin >= 0 && hin < HH && win >= 0 && win < WW)
                v = xb[(size_t)(ccb + c) * HWPIX + hin * WW + win];
            sx[c][rr][col] = v;
        }

        // Stage aggregated weights, interleaved by output-channel pair.
        for (int i = tid; i < (OT / 2) * CCH * 9; i += TPB) {
            int op  = i / (CCH * 9);              // pair index within tile
            int rem = i % (CCH * 9);
            int c   = rem / 9;
            int k   = rem % 9;
            size_t g0 = ((size_t)(obase + 2 * op)     * CIN + (ccb + c)) * 9 + k;
            size_t g1 = ((size_t)(obase + 2 * op + 1) * CIN + (ccb + c)) * 9 + k;
            swt2[op][rem] = make_float2(a0 * cw[g0] + a1 * dw[g0],
                                        a0 * cw[g1] + a1 * dw[g1]);
        }
        __syncthreads();

        #pragma unroll 1
        for (int c = 0; c < CCH; ++c) {
            // Broadcast-pack the 6x3 input window once per channel.
            unsigned long long xp[TH + 2][3];
            #pragma unroll
            for (int rr = 0; rr < TH + 2; ++rr)
                #pragma unroll
                for (int jj = 0; jj < 3; ++jj)
                    xp[rr][jj] = bcast2(sx[c][rr][tx + jj]);

            #pragma unroll
            for (int p = 0; p < 4; ++p) {
                const unsigned long long* wp =
                    reinterpret_cast<const unsigned long long*>(&swt2[ty * 4 + p][c * 9]);
                unsigned long long w[9];
                #pragma unroll
                for (int k = 0; k < 9; ++k) w[k] = wp[k];   // LDS.64, broadcast

                #pragma unroll
                for (int i3 = 0; i3 < 3; ++i3)
                    #pragma unroll
                    for (int j3 = 0; j3 < 3; ++j3)
                        #pragma unroll
                        for (int r = 0; r < TH; ++r)
                            fma2(acc2[r][p], xp[r + i3][j3], w[i3 * 3 + j3]);
            }
        }
    }

    // Epilogue: unpack, add aggregated bias, store.
    #pragma unroll
    for (int p = 0; p < 4; ++p) {
        int o0 = obase + ty * 8 + 2 * p;
        int o1 = o0 + 1;
        float b0 = a0 * cb[o0] + a1 * db[o0];
        float b1 = a0 * cb[o1] + a1 * db[o1];
        #pragma unroll
        for (int r = 0; r < TH; ++r) {
            float lo, hi;
            unpack2(acc2[r][p], lo, hi);
            out[(((size_t)b * OUTC + o0) * HH + (hbase + r)) * WW + tx] = lo + b0;
            out[(((size_t)b * OUTC + o1) * HH + (hbase + r)) * WW + tx] = hi + b1;
        }
    }
}

// ---------------------------------------------------------------------------
// Harness entry point.
// ---------------------------------------------------------------------------
extern "C" void kernel_launch(void* const* d_in, const int* in_sizes, int n_in,
                              void* d_out, int out_size)
{
    const float* x     = (const float*)d_in[0];
    const float* cw    = (const float*)d_in[1];
    const float* cb    = (const float*)d_in[2];
    const float* dw    = (const float*)d_in[3];
    const float* db    = (const float*)d_in[4];
    const float* fc1_w = (const float*)d_in[5];
    const float* fc2_w = (const float*)d_in[6];
    float* out = (float*)d_out;

    attn_kernel<<<BATCH, 256>>>(x, fc1_w, fc2_w);

    dim3 grid(HH / TH, OUTC / OT, BATCH);   // (14, 4, 32)
    dim3 block(WW, TH);                     // (56, 4) = 224 threads
    dyn_conv_kernel<<<grid, block>>>(x, cw, cb, dw, db, out);
}